// round 1
// baseline (speedup 1.0000x reference)
#include <cuda_runtime.h>
#include <math.h>

// ---------------- problem constants ----------------
constexpr int B_ = 2, T_ = 1024, H_ = 2048, NH_ = 8, NKV_ = 2, HD_ = 256;
constexpr int FF_ = 8192, LR_ = 64;
constexpr int BT_ = B_ * T_;                 // 2048 tokens
constexpr size_t BTH_ = (size_t)BT_ * H_;    // 4,194,304
constexpr float EPS_ = 1e-6f;

// ---------------- scratch (device global, no allocs) ----------------
struct Scratch {
    float pred[4 * BTH_];                  // AltUp predictions, 4 streams
    float xnorm[BTH_];
    float lrbuf[BT_ * LR_];
    float laurel[BTH_];
    float qraw[BTH_];
    float kraw[(size_t)BT_ * NKV_ * HD_];
    float vraw[(size_t)BT_ * NKV_ * HD_];
    float q[BTH_];                         // [B,NH,T,HD]
    float k[(size_t)BT_ * NKV_ * HD_];     // [B,NKV,T,HD]
    float vT[(size_t)BT_ * NKV_ * HD_];    // [B,NKV,HD,T]
    float scores[(size_t)B_ * NH_ * T_ * T_];
    float attnout[BTH_];                   // [B,T,NH*HD]
    float attnproj[BTH_];
    float attnlaurel[BTH_];
    float hn[BTH_];
    float gate[(size_t)BT_ * FF_];
    float up[(size_t)BT_ * FF_];
    float ffw[BTH_];
    float act[BTH_];
    float m[BT_ * 4];
    float mc[BT_ * 4];
};
__device__ Scratch g_scratch;

// ---------------- reductions ----------------
__device__ __forceinline__ float warpSum(float v) {
#pragma unroll
    for (int o = 16; o > 0; o >>= 1) v += __shfl_xor_sync(0xffffffffu, v, o);
    return v;
}
__device__ __forceinline__ float warpMax(float v) {
#pragma unroll
    for (int o = 16; o > 0; o >>= 1) v = fmaxf(v, __shfl_xor_sync(0xffffffffu, v, o));
    return v;
}
__device__ __forceinline__ float blockSum(float v, float* red) {
    v = warpSum(v);
    int lane = threadIdx.x & 31, w = threadIdx.x >> 5;
    if (lane == 0) red[w] = v;
    __syncthreads();
    int nw = (blockDim.x + 31) >> 5;
    float r = (lane < nw) ? red[lane] : 0.f;
    if (w == 0) { r = warpSum(r); if (lane == 0) red[0] = r; }
    __syncthreads();
    r = red[0];
    __syncthreads();
    return r;
}
__device__ __forceinline__ float blockMax(float v, float* red) {
    v = warpMax(v);
    int lane = threadIdx.x & 31, w = threadIdx.x >> 5;
    if (lane == 0) red[w] = v;
    __syncthreads();
    int nw = (blockDim.x + 31) >> 5;
    float r = (lane < nw) ? red[lane] : -INFINITY;
    if (w == 0) { r = warpMax(r); if (lane == 0) red[0] = r; }
    __syncthreads();
    r = red[0];
    __syncthreads();
    return r;
}

// ---------------- LayerNorm (Gemma3n RMS-style: center, rsqrt(var), *w) ----------------
// dst = scale * ( LN(a)*w + add1? + add2? )
__global__ void ln_kernel(const float* __restrict__ a, const float* __restrict__ w,
                          const float* __restrict__ add1, const float* __restrict__ add2,
                          float scale, float* __restrict__ dst) {
    __shared__ float sx[H_];
    __shared__ float red[32];
    size_t off = (size_t)blockIdx.x * H_;
    int tid = threadIdx.x;
    float ls = 0.f;
    for (int i = tid; i < H_; i += blockDim.x) { float v = a[off + i]; sx[i] = v; ls += v; }
    float mean = blockSum(ls, red) * (1.f / H_);
    float lv = 0.f;
    for (int i = tid; i < H_; i += blockDim.x) { float d = sx[i] - mean; lv += d * d; }
    float var = blockSum(lv, red) * (1.f / H_);
    float rs = rsqrtf(var + EPS_);
    for (int i = tid; i < H_; i += blockDim.x) {
        float v = (sx[i] - mean) * rs * w[i];
        if (add1) v += add1[off + i];
        if (add2) v += add2[off + i];
        dst[off + i] = v * scale;
    }
}

// ---------------- router / modalities: tanh((LN(x)*w/H) @ router_w^T) ----------------
__global__ void router_kernel(const float* __restrict__ x, const float* __restrict__ nw,
                              const float* __restrict__ rw, float* __restrict__ m) {
    __shared__ float sx[H_];
    __shared__ float red[32];
    size_t off = (size_t)blockIdx.x * H_;
    int tid = threadIdx.x;
    float ls = 0.f;
    for (int i = tid; i < H_; i += blockDim.x) { float v = x[off + i]; sx[i] = v; ls += v; }
    float mean = blockSum(ls, red) * (1.f / H_);
    float lv = 0.f;
    for (int i = tid; i < H_; i += blockDim.x) { float d = sx[i] - mean; lv += d * d; }
    float rs = rsqrtf(blockSum(lv, red) * (1.f / H_) + EPS_);
    float a0 = 0, a1 = 0, a2 = 0, a3 = 0;
    for (int i = tid; i < H_; i += blockDim.x) {
        float r = (sx[i] - mean) * rs * nw[i] * (1.f / H_);
        a0 += r * rw[i];
        a1 += r * rw[H_ + i];
        a2 += r * rw[2 * H_ + i];
        a3 += r * rw[3 * H_ + i];
    }
    float t0 = blockSum(a0, red);
    float t1 = blockSum(a1, red);
    float t2 = blockSum(a2, red);
    float t3 = blockSum(a3, red);
    if (tid == 0) {
        m[blockIdx.x * 4 + 0] = tanhf(t0);
        m[blockIdx.x * 4 + 1] = tanhf(t1);
        m[blockIdx.x * 4 + 2] = tanhf(t2);
        m[blockIdx.x * 4 + 3] = tanhf(t3);
    }
}

// ---------------- AltUp predict ----------------
__global__ void predict_kernel(const float* __restrict__ hs, const float* __restrict__ m,
                               const float* __restrict__ pcw, float* __restrict__ pred) {
    __shared__ float cf[16];
    int token = blockIdx.x, tid = threadIdx.x;
    if (tid < 16) {
        float s = 0.f;
#pragma unroll
        for (int i = 0; i < 4; i++) s += m[token * 4 + i] * pcw[tid * 4 + i];
        cf[tid] = s;
    }
    __syncthreads();
    size_t off = (size_t)token * H_;
    for (int f = tid; f < H_; f += blockDim.x) {
        float h0 = hs[off + f], h1 = hs[BTH_ + off + f];
        float h2 = hs[2 * BTH_ + off + f], h3 = hs[3 * BTH_ + off + f];
        float hv[4] = {h0, h1, h2, h3};
#pragma unroll
        for (int j = 0; j < 4; j++) {
            float p = hv[j] + h0 * cf[j * 4 + 0] + h1 * cf[j * 4 + 1]
                            + h2 * cf[j * 4 + 2] + h3 * cf[j * 4 + 3];
            pred[(size_t)j * BTH_ + off + f] = p;
        }
    }
}

// ---------------- AltUp correct + output scale ----------------
__global__ void correct_kernel(const float* __restrict__ act, const float* __restrict__ pred,
                               const float* __restrict__ mc, const float* __restrict__ ccw,
                               const float* __restrict__ cscale, float* __restrict__ out) {
    __shared__ float cc[4];
    int token = blockIdx.x, tid = threadIdx.x;
    if (tid < 4) {
        float s = 1.f;
#pragma unroll
        for (int i = 0; i < 4; i++) s += mc[token * 4 + i] * ccw[tid * 4 + i];
        cc[tid] = s;
    }
    __syncthreads();
    size_t off = (size_t)token * H_;
    for (int f = tid; f < H_; f += blockDim.x) {
        float p0 = pred[off + f];
        float inno = act[off + f] - p0;
#pragma unroll
        for (int j = 0; j < 4; j++) {
            float v = inno * cc[j] + pred[(size_t)j * BTH_ + off + f];
            if (j == 0) v *= cscale[f];
            out[(size_t)j * BTH_ + off + f] = v;
        }
    }
}

// ---------------- per-head LN (+rope) for q/k/v, layout shuffle ----------------
__global__ void qkvpost_kernel(const float* __restrict__ raw, const float* __restrict__ nw,
                               const float* __restrict__ cosb, const float* __restrict__ sinb,
                               float* __restrict__ out, int nheads, int do_rope, int trans) {
    __shared__ float sx[HD_];
    __shared__ float red[32];
    int idx = blockIdx.x;
    int h = idx % nheads;
    int bt = idx / nheads;
    int t = bt % T_, b = bt / T_;
    int d = threadIdx.x;
    float v = raw[(size_t)bt * nheads * HD_ + h * HD_ + d];
    float mean = blockSum(v, red) * (1.f / HD_);
    float c = v - mean;
    float var = blockSum(c * c, red) * (1.f / HD_);
    float ln = c * rsqrtf(var + EPS_) * (nw ? nw[d] : 1.f);
    sx[d] = ln;
    __syncthreads();
    float o = ln;
    if (do_rope) {
        float cs = cosb[(size_t)bt * HD_ + d];
        float sn = sinb[(size_t)bt * HD_ + d];
        float rot = (d < 128) ? -sx[d + 128] : sx[d - 128];
        o = ln * cs + rot * sn;
    }
    if (trans) out[((size_t)(b * nheads + h) * HD_ + d) * T_ + t] = o;       // [B,nh,HD,T]
    else       out[((size_t)(b * nheads + h) * T_ + t) * HD_ + d] = o;       // [B,nh,T,HD]
}

// ---------------- causal softmax (row-wise, fp32) ----------------
__global__ void softmax_kernel(float* __restrict__ scores) {
    __shared__ float sx[T_];
    __shared__ float red[32];
    int q = blockIdx.x % T_;
    size_t off = (size_t)blockIdx.x * T_;
    int tid = threadIdx.x;
    int n = q + 1;
    float lm = -INFINITY;
    for (int i = tid; i < n; i += blockDim.x) { float v = scores[off + i]; sx[i] = v; lm = fmaxf(lm, v); }
    float gm = blockMax(lm, red);
    float lsum = 0.f;
    for (int i = tid; i < n; i += blockDim.x) { float e = __expf(sx[i] - gm); sx[i] = e; lsum += e; }
    float inv = 1.f / blockSum(lsum, red);
    for (int i = tid; i < T_; i += blockDim.x) scores[off + i] = (i < n) ? sx[i] * inv : 0.f;
}

// ---------------- gelu(tanh)*up, in place into g ----------------
__global__ void gelumul_kernel(float* __restrict__ g, const float* __restrict__ u, size_t n4) {
    size_t i = (size_t)blockIdx.x * blockDim.x + threadIdx.x;
    if (i >= n4) return;
    float4 a = reinterpret_cast<float4*>(g)[i];
    float4 b = reinterpret_cast<const float4*>(u)[i];
#define GELU_(x) (0.5f * (x) * (1.f + tanhf(0.7978845608028654f * ((x) + 0.044715f * (x) * (x) * (x)))))
    a.x = GELU_(a.x) * b.x;
    a.y = GELU_(a.y) * b.y;
    a.z = GELU_(a.z) * b.z;
    a.w = GELU_(a.w) * b.w;
#undef GELU_
    reinterpret_cast<float4*>(g)[i] = a;
}

// ---------------- generic SGEMM core: C = A[M,K] @ B[N,K]^T ----------------
constexpr int GBM = 128, GBN = 128, GBK = 16;

__device__ __forceinline__ void gemm_core(
    const float* __restrict__ A, const float* __restrict__ B, float* __restrict__ C,
    int M, int N, int K, int lda, int ldb, int ldc, int bm, int bn,
    float (&As)[GBK][GBM + 4], float (&Bs)[GBK][GBN + 4]) {
    int tid = threadIdx.x;
    int tx = tid & 15, ty = tid >> 4;
    float acc[8][8];
#pragma unroll
    for (int i = 0; i < 8; i++)
#pragma unroll
        for (int j = 0; j < 8; j++) acc[i][j] = 0.f;

    int lr = tid >> 2;           // 0..63
    int lk = (tid & 3) << 2;     // 0,4,8,12

    for (int k0 = 0; k0 < K; k0 += GBK) {
#pragma unroll
        for (int r = 0; r < 2; r++) {
            int row = bm + lr + r * 64;
            float4 a4 = make_float4(0.f, 0.f, 0.f, 0.f);
            if (row < M) a4 = *reinterpret_cast<const float4*>(&A[(size_t)row * lda + k0 + lk]);
            As[lk + 0][lr + r * 64] = a4.x;
            As[lk + 1][lr + r * 64] = a4.y;
            As[lk + 2][lr + r * 64] = a4.z;
            As[lk + 3][lr + r * 64] = a4.w;
            int rowb = bn + lr + r * 64;
            float4 b4 = make_float4(0.f, 0.f, 0.f, 0.f);
            if (rowb < N) b4 = *reinterpret_cast<const float4*>(&B[(size_t)rowb * ldb + k0 + lk]);
            Bs[lk + 0][lr + r * 64] = b4.x;
            Bs[lk + 1][lr + r * 64] = b4.y;
            Bs[lk + 2][lr + r * 64] = b4.z;
            Bs[lk + 3][lr + r * 64] = b4.w;
        }
        __syncthreads();
#pragma unroll
        for (int kk = 0; kk < GBK; kk++) {
            float ar[8], br[8];
            *(float4*)&ar[0] = *(const float4*)&As[kk][ty * 8];
            *(float4*)&ar[4] = *(const float4*)&As[kk][ty * 8 + 4];
            *(float4*)&br[0] = *(const float4*)&Bs[kk][tx * 8];
            *(float4*)&br[4] = *(const float4*)&Bs[kk][tx * 8 + 4];
#pragma unroll
            for (int i = 0; i < 8; i++)
#pragma unroll
                for (int j = 0; j < 8; j++)
                    acc[i][j] = fmaf(ar[i], br[j], acc[i][j]);
        }
        __syncthreads();
    }
#pragma unroll
    for (int i = 0; i < 8; i++) {
        int row = bm + ty * 8 + i;
        if (row >= M) continue;
#pragma unroll
        for (int j = 0; j < 8; j++) {
            int col = bn + tx * 8 + j;
            if (col < N) C[(size_t)row * ldc + col] = acc[i][j];
        }
    }
}

__global__ void __launch_bounds__(256, 2)
sgemm_nt(const float* __restrict__ A, const float* __restrict__ B, float* __restrict__ C,
         int M, int N, int K, int lda, int ldb, int ldc) {
    __shared__ float As[GBK][GBM + 4];
    __shared__ float Bs[GBK][GBN + 4];
    gemm_core(A, B, C, M, N, K, lda, ldb, ldc, blockIdx.y * GBM, blockIdx.x * GBN, As, Bs);
}

// scores[z] = q[z] @ k[kv(z)]^T, causal tile skip
__global__ void __launch_bounds__(256, 2)
scores_gemm(const float* __restrict__ q, const float* __restrict__ k, float* __restrict__ s) {
    if (blockIdx.x > blockIdx.y) return;  // entire tile above diagonal
    int z = blockIdx.z;
    int b = z >> 3, h = z & 7;
    const float* A = q + (size_t)z * T_ * HD_;
    const float* B = k + (size_t)(b * NKV_ + (h >> 2)) * T_ * HD_;
    float* C = s + (size_t)z * T_ * T_;
    __shared__ float As[GBK][GBM + 4];
    __shared__ float Bs[GBK][GBN + 4];
    gemm_core(A, B, C, T_, T_, HD_, HD_, HD_, T_, blockIdx.y * GBM, blockIdx.x * GBN, As, Bs);
}

// attnout[b,t, h*HD+d] = sum_k attn[z][t,k] * vT[kv(z)][d,k], K bounded by causal diag
__global__ void __launch_bounds__(256, 2)
attnv_gemm(const float* __restrict__ p, const float* __restrict__ vT, float* __restrict__ o) {
    int z = blockIdx.z;
    int b = z >> 3, h = z & 7;
    const float* A = p + (size_t)z * T_ * T_;
    const float* B = vT + (size_t)(b * NKV_ + (h >> 2)) * HD_ * T_;
    float* C = o + (size_t)b * T_ * H_ + (size_t)h * HD_;
    int bm = blockIdx.y * GBM;
    int Keff = bm + GBM;  // rows in this tile only attend to k <= bm+127; rest is zero
    __shared__ float As[GBK][GBM + 4];
    __shared__ float Bs[GBK][GBN + 4];
    gemm_core(A, B, C, T_, HD_, Keff, T_, T_, H_, bm, blockIdx.x * GBN, As, Bs);
}

// ---------------- launch ----------------
extern "C" void kernel_launch(void* const* d_in, const int* in_sizes, int n_in,
                              void* d_out, int out_size) {
    const float* hs    = (const float*)d_in[0];   // [4,B,T,H]
    const float* cosb  = (const float*)d_in[1];   // [B,T,HD]
    const float* sinb  = (const float*)d_in[2];
    const float* wq    = (const float*)d_in[3];
    const float* wk    = (const float*)d_in[4];
    const float* wv    = (const float*)d_in[5];
    const float* wo    = (const float*)d_in[6];
    const float* qnw   = (const float*)d_in[7];
    const float* knw   = (const float*)d_in[8];
    const float* in_ln = (const float*)d_in[9];
    const float* pa_ln = (const float*)d_in[10];
    const float* pf_ln = (const float*)d_in[11];
    const float* pw_ln = (const float*)d_in[12];
    const float* gatew = (const float*)d_in[13];
    const float* upw   = (const float*)d_in[14];
    const float* downw = (const float*)d_in[15];
    const float* llw   = (const float*)d_in[16];
    const float* lrw   = (const float*)d_in[17];
    const float* lnw   = (const float*)d_in[18];
    const float* rnw   = (const float*)d_in[19];
    const float* rw    = (const float*)d_in[20];
    const float* pcw   = (const float*)d_in[21];
    const float* ccw   = (const float*)d_in[22];
    const float* cscal = (const float*)d_in[23];
    float* out = (float*)d_out;

    Scratch* S = nullptr;
    cudaGetSymbolAddress((void**)&S, g_scratch);

    // 1. router on stream 0 -> m
    router_kernel<<<BT_, 256>>>(hs, rnw, rw, S->m);
    // 2. AltUp predict -> pred[0..3]
    predict_kernel<<<BT_, 256>>>(hs, S->m, pcw, S->pred);
    // 3. x_norm = LN(pred0)
    ln_kernel<<<BT_, 256>>>(S->pred, in_ln, nullptr, nullptr, 1.f, S->xnorm);
    // 4. laurel: xnorm @ llw^T -> lrbuf [2048,64]
    sgemm_nt<<<dim3(1, 16), 256>>>(S->xnorm, llw, S->lrbuf, BT_, LR_, H_, H_, H_, LR_);
    // 5. lrbuf @ lrw^T -> laurel raw [2048,2048]
    sgemm_nt<<<dim3(16, 16), 256>>>(S->lrbuf, lrw, S->laurel, BT_, H_, LR_, LR_, LR_, H_);
    // 6. laurel_out = xnorm + LN(laurel)  (in place)
    ln_kernel<<<BT_, 256>>>(S->laurel, lnw, S->xnorm, nullptr, 1.f, S->laurel);
    // 7. QKV projections
    sgemm_nt<<<dim3(16, 16), 256>>>(S->xnorm, wq, S->qraw, BT_, NH_ * HD_, H_, H_, H_, NH_ * HD_);
    sgemm_nt<<<dim3(4, 16), 256>>>(S->xnorm, wk, S->kraw, BT_, NKV_ * HD_, H_, H_, H_, NKV_ * HD_);
    sgemm_nt<<<dim3(4, 16), 256>>>(S->xnorm, wv, S->vraw, BT_, NKV_ * HD_, H_, H_, H_, NKV_ * HD_);
    // 8. per-head LN (+rope), layout shuffles
    qkvpost_kernel<<<BT_ * NH_, 256>>>(S->qraw, qnw, cosb, sinb, S->q, NH_, 1, 0);
    qkvpost_kernel<<<BT_ * NKV_, 256>>>(S->kraw, knw, cosb, sinb, S->k, NKV_, 1, 0);
    qkvpost_kernel<<<BT_ * NKV_, 256>>>(S->vraw, nullptr, cosb, sinb, S->vT, NKV_, 0, 1);
    // 9. scores = q @ k^T (causal tiles only)
    scores_gemm<<<dim3(8, 8, B_ * NH_), 256>>>(S->q, S->k, S->scores);
    // 10. causal softmax
    softmax_kernel<<<B_ * NH_ * T_, 256>>>(S->scores);
    // 11. attn @ v -> attnout [B,T,NH*HD]
    attnv_gemm<<<dim3(2, 8, B_ * NH_), 256>>>(S->scores, S->vT, S->attnout);
    // 12. output projection
    sgemm_nt<<<dim3(16, 16), 256>>>(S->attnout, wo, S->attnproj, BT_, H_, NH_ * HD_, NH_ * HD_, NH_ * HD_, H_);
    // 13. attn_laurel = (pred0 + laurel_out + LN(attnproj)) / sqrt(2)
    ln_kernel<<<BT_, 256>>>(S->attnproj, pa_ln, S->pred, S->laurel, 0.7071067811865476f, S->attnlaurel);
    // 14. h = LN(attn_laurel)
    ln_kernel<<<BT_, 256>>>(S->attnlaurel, pf_ln, nullptr, nullptr, 1.f, S->hn);
    // 15/16. gate & up GEMMs
    sgemm_nt<<<dim3(64, 16), 256>>>(S->hn, gatew, S->gate, BT_, FF_, H_, H_, H_, FF_);
    sgemm_nt<<<dim3(64, 16), 256>>>(S->hn, upw, S->up, BT_, FF_, H_, H_, H_, FF_);
    // 17. gelu(gate)*up -> gate
    {
        size_t n4 = ((size_t)BT_ * FF_) / 4;
        gelumul_kernel<<<(unsigned)((n4 + 255) / 256), 256>>>(S->gate, S->up, n4);
    }
    // 18. down GEMM
    sgemm_nt<<<dim3(16, 16), 256>>>(S->gate, downw, S->ffw, BT_, H_, FF_, FF_, FF_, H_);
    // 19. activated = attn_laurel + LN(ffw)
    ln_kernel<<<BT_, 256>>>(S->ffw, pw_ln, S->attnlaurel, nullptr, 1.f, S->act);
    // 20. router on activated -> mc
    router_kernel<<<BT_, 256>>>(S->act, rnw, rw, S->mc);
    // 21. AltUp correct + output scale -> d_out [4,B,T,H]
    correct_kernel<<<BT_, 256>>>(S->act, S->pred, S->mc, ccw, cscal, out);

    (void)in_sizes; (void)n_in; (void)out_size;
}

// round 4
// speedup vs baseline: 2.1752x; 2.1752x over previous
#include <cuda_runtime.h>
#include <cstdint>
#include <cstddef>
#include <math.h>

constexpr int B_ = 2, T_ = 1024, H_ = 2048, NH_ = 8, NKV_ = 2, HD_ = 256;
constexpr int FF_ = 8192, LR_ = 64;
constexpr int BT_ = B_ * T_;
constexpr size_t BTH_ = (size_t)BT_ * H_;
constexpr float EPS_ = 1e-6f;

struct Scratch {
    float pred[4 * BTH_];
    float xnorm[BTH_];
    float lrpart[4 * BT_ * LR_];
    float lrbuf[BT_ * LR_];
    float laurel[BTH_];
    float qraw[BTH_];
    float kraw[(size_t)BT_ * NKV_ * HD_];
    float vraw[(size_t)BT_ * NKV_ * HD_];
    float q[BTH_];
    float k[(size_t)BT_ * NKV_ * HD_];
    float vT[(size_t)BT_ * NKV_ * HD_];
    float scores[(size_t)B_ * NH_ * T_ * T_];
    float attnout[BTH_];
    float attnproj[BTH_];
    float attnlaurel[BTH_];
    float hn[BTH_];
    float gate[(size_t)BT_ * FF_];
    float up[(size_t)BT_ * FF_];
    float ffw[BTH_];
    float act[BTH_];
    float m[BT_ * 4];
    float mc[BT_ * 4];
};
__device__ Scratch g_scratch;

__device__ __forceinline__ float warpSum(float v) {
#pragma unroll
    for (int o = 16; o > 0; o >>= 1) v += __shfl_xor_sync(0xffffffffu, v, o);
    return v;
}

__device__ __forceinline__ float warpMax(float v) {
#pragma unroll
    for (int o = 16; o > 0; o >>= 1) v = fmaxf(v, __shfl_xor_sync(0xffffffffu, v, o));
    return v;
}

__device__ __forceinline__ float blockSum(float v, float* red) {
    v = warpSum(v);
    int lane = threadIdx.x & 31, w = threadIdx.x >> 5;
    if (lane == 0) red[w] = v;
    __syncthreads();
    int nw = (blockDim.x + 31) >> 5;
    float r = (lane < nw) ? red[lane] : 0.f;
    if (w == 0) {
        r = warpSum(r);
        if (lane == 0) red[0] = r;
    }
    __syncthreads();
    r = red[0];
    __syncthreads();
    return r;
}

__device__ __forceinline__ float blockMax(float v, float* red) {
    v = warpMax(v);
    int lane = threadIdx.x & 31, w = threadIdx.x >> 5;
    if (lane == 0) red[w] = v;
    __syncthreads();
    int nw = (blockDim.x + 31) >> 5;
    float r = (lane < nw) ? red[lane] : -INFINITY;
    if (w == 0) {
        r = warpMax(r);
        if (lane == 0) red[0] = r;
    }
    __syncthreads();
    r = red[0];
    __syncthreads();
    return r;
}

__global__ void ln_kernel(const float* __restrict__ a, const float* __restrict__ w,
                          const float* __restrict__ add1, const float* __restrict__ add2,
                          float scale, float* __restrict__ dst) {
    __shared__ float sx[H_];
    __shared__ float red[32];
    size_t off = (size_t)blockIdx.x * H_;
    int tid = threadIdx.x;
    float ls = 0.f;
    for (int i = tid; i < H_; i += blockDim.x) {
        float v = a[off + i];
        sx[i] = v;
        ls += v;
    }
    float mean = blockSum(ls, red) * (1.f / H_);
    float lv = 0.f;
    for (int i = tid; i < H_; i += blockDim.x) {
        float d = sx[i] - mean;
        lv += d * d;
    }
    float var = blockSum(lv, red) * (1.f / H_);
    float rs = rsqrtf(var + EPS_);
    for (int i = tid; i < H_; i += blockDim.x) {
        float v = (sx[i] - mean) * rs * w[i];
        if (add1) v += add1[off + i];
        if (add2) v += add2[off + i];
        dst[off + i] = v * scale;
    }
}

__global__ void router_kernel(const float* __restrict__ x, const float* __restrict__ nw,
                              const float* __restrict__ rw, float* __restrict__ m) {
    __shared__ float sx[H_];
    __shared__ float red[32];
    size_t off = (size_t)blockIdx.x * H_;
    int tid = threadIdx.x;
    float ls = 0.f;
    for (int i = tid; i < H_; i += blockDim.x) {
        float v = x[off + i];
        sx[i] = v;
        ls += v;
    }
    float mean = blockSum(ls, red) * (1.f / H_);
    float lv = 0.f;
    for (int i = tid; i < H_; i += blockDim.x) {
        float d = sx[i] - mean;
        lv += d * d;
    }
    float rs = rsqrtf(blockSum(lv, red) * (1.f / H_) + EPS_);
    float a0 = 0.f, a1 = 0.f, a2 = 0.f, a3 = 0.f;
    for (int i = tid; i < H_; i += blockDim.x) {
        float r = (sx[i] - mean) * rs * nw[i] * (1.f / H_);
        a0 += r * rw[i];
        a1 += r * rw[H_ + i];
        a2 += r * rw[2 * H_ + i];
        a3 += r * rw[3 * H_ + i];
    }
    float t0 = blockSum(a0, red);
    float t1 = blockSum(a1, red);
    float t2 = blockSum(a2, red);
    float t3 = blockSum(a3, red);
    if (tid == 0) {
        m[blockIdx.x * 4 + 0] = tanhf(t0);
        m[blockIdx.x * 4 + 1] = tanhf(t1);
        m[blockIdx.x * 4 + 2] = tanhf(t2);
        m[blockIdx.x * 4 + 3] = tanhf(t3);
    }
}

__global__ void predict_kernel(const float* __restrict__ hs, const float* __restrict__ m,
                               const float* __restrict__ pcw, float* __restrict__ pred) {
    __shared__ float cf[16];
    int token = blockIdx.x, tid = threadIdx.x;
    if (tid < 16) {
        float s = 0.f;
#pragma unroll
        for (int i = 0; i < 4; i++) s += m[token * 4 + i] * pcw[tid * 4 + i];
        cf[tid] = s;
    }
    __syncthreads();
    size_t off = (size_t)token * H_;
    for (int f = tid; f < H_; f += blockDim.x) {
        float h0 = hs[off + f];
        float h1 = hs[BTH_ + off + f];
        float h2 = hs[2 * BTH_ + off + f];
        float h3 = hs[3 * BTH_ + off + f];
        float hv0 = h0, hv1 = h1, hv2 = h2, hv3 = h3;
        pred[off + f]            = hv0 + h0 * cf[0]  + h1 * cf[1]  + h2 * cf[2]  + h3 * cf[3];
        pred[BTH_ + off + f]     = hv1 + h0 * cf[4]  + h1 * cf[5]  + h2 * cf[6]  + h3 * cf[7];
        pred[2 * BTH_ + off + f] = hv2 + h0 * cf[8]  + h1 * cf[9]  + h2 * cf[10] + h3 * cf[11];
        pred[3 * BTH_ + off + f] = hv3 + h0 * cf[12] + h1 * cf[13] + h2 * cf[14] + h3 * cf[15];
    }
}

__global__ void correct_kernel(const float* __restrict__ act, const float* __restrict__ pred,
                               const float* __restrict__ mc, const float* __restrict__ ccw,
                               const float* __restrict__ cscale, float* __restrict__ out) {
    __shared__ float cc[4];
    int token = blockIdx.x, tid = threadIdx.x;
    if (tid < 4) {
        float s = 1.f;
#pragma unroll
        for (int i = 0; i < 4; i++) s += mc[token * 4 + i] * ccw[tid * 4 + i];
        cc[tid] = s;
    }
    __syncthreads();
    size_t off = (size_t)token * H_;
    for (int f = tid; f < H_; f += blockDim.x) {
        float p0 = pred[off + f];
        float inno = act[off + f] - p0;
        out[off + f]            = (inno * cc[0] + p0) * cscale[f];
        out[BTH_ + off + f]     = inno * cc[1] + pred[BTH_ + off + f];
        out[2 * BTH_ + off + f] = inno * cc[2] + pred[2 * BTH_ + off + f];
        out[3 * BTH_ + off + f] = inno * cc[3] + pred[3 * BTH_ + off + f];
    }
}

__global__ void qkvpost_kernel(const float* __restrict__ raw, const float* __restrict__ nw,
                               const float* __restrict__ cosb, const float* __restrict__ sinb,
                               float* __restrict__ out, int nheads, int do_rope, int trans) {
    __shared__ float sx[HD_];
    __shared__ float red[32];
    int idx = blockIdx.x;
    int h = idx % nheads;
    int bt = idx / nheads;
    int t = bt % T_, b = bt / T_;
    int d = threadIdx.x;
    float v = raw[(size_t)bt * nheads * HD_ + h * HD_ + d];
    float mean = blockSum(v, red) * (1.f / HD_);
    float c = v - mean;
    float var = blockSum(c * c, red) * (1.f / HD_);
    float ln = c * rsqrtf(var + EPS_) * (nw ? nw[d] : 1.f);
    sx[d] = ln;
    __syncthreads();
    float o = ln;
    if (do_rope) {
        float cs = cosb[(size_t)bt * HD_ + d];
        float sn = sinb[(size_t)bt * HD_ + d];
        float rot = (d < 128) ? -sx[d + 128] : sx[d - 128];
        o = ln * cs + rot * sn;
    }
    if (trans) {
        out[((size_t)(b * nheads + h) * HD_ + d) * T_ + t] = o;
    } else {
        out[((size_t)(b * nheads + h) * T_ + t) * HD_ + d] = o;
    }
}

__global__ void softmax_kernel(float* __restrict__ scores) {
    __shared__ float sx[T_];
    __shared__ float red[32];
    int q = blockIdx.x % T_;
    size_t off = (size_t)blockIdx.x * T_;
    int tid = threadIdx.x;
    int n = q + 1;
    float lm = -INFINITY;
    for (int i = tid; i < n; i += blockDim.x) {
        float v = scores[off + i];
        sx[i] = v;
        lm = fmaxf(lm, v);
    }
    float gm = blockMax(lm, red);
    float lsum = 0.f;
    for (int i = tid; i < n; i += blockDim.x) {
        float e = __expf(sx[i] - gm);
        sx[i] = e;
        lsum += e;
    }
    float inv = 1.f / blockSum(lsum, red);
    for (int i = tid; i < T_; i += blockDim.x) {
        scores[off + i] = (i < n) ? sx[i] * inv : 0.f;
    }
}

__device__ __forceinline__ float gelu_tanh(float x) {
    return 0.5f * x * (1.f + tanhf(0.7978845608028654f * (x + 0.044715f * x * x * x)));
}

__global__ void gelumul_kernel(float* __restrict__ g, const float* __restrict__ u, int n4) {
    int i = blockIdx.x * blockDim.x + threadIdx.x;
    if (i >= n4) return;
    float4 a = reinterpret_cast<float4*>(g)[i];
    float4 b = reinterpret_cast<const float4*>(u)[i];
    a.x = gelu_tanh(a.x) * b.x;
    a.y = gelu_tanh(a.y) * b.y;
    a.z = gelu_tanh(a.z) * b.z;
    a.w = gelu_tanh(a.w) * b.w;
    reinterpret_cast<float4*>(g)[i] = a;
}

// ===== bf16 helpers (bit-level, no cuda_bf16.h dependency) =====
__device__ __forceinline__ uint32_t f2bf(float x) {
    uint32_t u = __float_as_uint(x);
    return (u + 0x7FFFu + ((u >> 16) & 1u)) >> 16;   // round to nearest even
}
__device__ __forceinline__ float bf2f(uint32_t b) {
    return __uint_as_float(b << 16);
}

// ===== bf16-split tensor-core GEMM: C = A[M,K] @ B[N,K]^T (fp32 in/out) =====
constexpr int MBM = 128, MBN = 128, MBK = 32;
constexpr int MLDW = 20;   // words per smem row (= 40 bf16 = 80 bytes, conflict-free)

struct MSmem {
    uint32_t Ah[MBM][MLDW];
    uint32_t Al[MBM][MLDW];
    uint32_t Bh[MBN][MLDW];
    uint32_t Bl[MBN][MLDW];
};

__device__ __forceinline__ void ldsm4(uint32_t* r, uint32_t addr) {
    asm volatile("ldmatrix.sync.aligned.m8n8.x4.shared.b16 {%0,%1,%2,%3}, [%4];"
                 : "=r"(r[0]), "=r"(r[1]), "=r"(r[2]), "=r"(r[3]) : "r"(addr));
}

__device__ __forceinline__ void mma16816(float* d, const uint32_t* a, uint32_t b0, uint32_t b1) {
    asm volatile("mma.sync.aligned.m16n8k16.row.col.f32.bf16.bf16.f32 "
                 "{%0,%1,%2,%3}, {%4,%5,%6,%7}, {%8,%9}, {%0,%1,%2,%3};"
                 : "+f"(d[0]), "+f"(d[1]), "+f"(d[2]), "+f"(d[3])
                 : "r"(a[0]), "r"(a[1]), "r"(a[2]), "r"(a[3]), "r"(b0), "r"(b1));
}

__device__ __forceinline__ void splitStore(float4 v, uint32_t* hi, uint32_t* lo) {
    uint32_t hx = f2bf(v.x), hy = f2bf(v.y), hz = f2bf(v.z), hw = f2bf(v.w);
    uint32_t lx = f2bf(v.x - bf2f(hx));
    uint32_t ly = f2bf(v.y - bf2f(hy));
    uint32_t lz = f2bf(v.z - bf2f(hz));
    uint32_t lw = f2bf(v.w - bf2f(hw));
    hi[0] = hx | (hy << 16);
    hi[1] = hz | (hw << 16);
    lo[0] = lx | (ly << 16);
    lo[1] = lz | (lw << 16);
}

__device__ __forceinline__ void mma_core(
    const float* __restrict__ A, const float* __restrict__ B, float* __restrict__ C,
    int K, int lda, int ldb, int ldc, int bm, int bn, MSmem& s)
{
    const int tid = threadIdx.x;
    const int lane = tid & 31, wid = tid >> 5;
    const int wm = wid & 3, wn = wid >> 2;    // 4x2 warps; warp tile 32x64

    float acc[2][8][4];
#pragma unroll
    for (int i = 0; i < 2; i++) {
#pragma unroll
        for (int j = 0; j < 8; j++) {
#pragma unroll
            for (int e = 0; e < 4; e++) acc[i][j][e] = 0.f;
        }
    }

    const int lr = tid >> 3;          // 0..31
    const int lc = (tid & 7) * 4;     // element col 0..28
    const int wc = (tid & 7) * 2;     // word col 0..14

    const uint32_t sb = (uint32_t)__cvta_generic_to_shared(&s);
    const uint32_t offAl = MBM * MLDW * 4;
    const uint32_t offBh = 2 * MBM * MLDW * 4;
    const uint32_t offBl = 3 * MBM * MLDW * 4;
    const int arow = wm * 32 + (lane & 15);
    const int acol = (lane >> 4) * 8;
    const int brow = wn * 64 + (lane & 7) + ((lane >> 4) << 3);
    const int bcol = ((lane >> 3) & 1) << 3;

    for (int k0 = 0; k0 < K; k0 += MBK) {
#pragma unroll
        for (int p = 0; p < 4; p++) {
            int r = lr + p * 32;
            float4 av = *reinterpret_cast<const float4*>(&A[(size_t)(bm + r) * lda + k0 + lc]);
            splitStore(av, &s.Ah[r][wc], &s.Al[r][wc]);
            float4 bv = *reinterpret_cast<const float4*>(&B[(size_t)(bn + r) * ldb + k0 + lc]);
            splitStore(bv, &s.Bh[r][wc], &s.Bl[r][wc]);
        }
        __syncthreads();

#pragma unroll
        for (int kk = 0; kk < 2; kk++) {
            uint32_t ah[2][4], al[2][4], bh[4][4], bl[4][4];
#pragma unroll
            for (int mf = 0; mf < 2; mf++) {
                uint32_t ao = (uint32_t)(((arow + mf * 16) * MLDW * 4) + (kk * 16 + acol) * 2);
                ldsm4(ah[mf], sb + ao);
                ldsm4(al[mf], sb + offAl + ao);
            }
#pragma unroll
            for (int np = 0; np < 4; np++) {
                uint32_t bo = (uint32_t)(((brow + np * 16) * MLDW * 4) + (kk * 16 + bcol) * 2);
                ldsm4(bh[np], sb + offBh + bo);
                ldsm4(bl[np], sb + offBl + bo);
            }
#pragma unroll
            for (int mf = 0; mf < 2; mf++) {
#pragma unroll
                for (int nf = 0; nf < 8; nf++) {
                    int np = nf >> 1;
                    int hf = (nf & 1) * 2;
                    mma16816(acc[mf][nf], ah[mf], bh[np][hf], bh[np][hf + 1]);
                    mma16816(acc[mf][nf], al[mf], bh[np][hf], bh[np][hf + 1]);
                    mma16816(acc[mf][nf], ah[mf], bl[np][hf], bl[np][hf + 1]);
                }
            }
        }
        __syncthreads();
    }

#pragma unroll
    for (int mf = 0; mf < 2; mf++) {
        int row = bm + wm * 32 + mf * 16 + (lane >> 2);
#pragma unroll
        for (int nf = 0; nf < 8; nf++) {
            int col = bn + wn * 64 + nf * 8 + (lane & 3) * 2;
            *reinterpret_cast<float2*>(&C[(size_t)row * ldc + col]) =
                make_float2(acc[mf][nf][0], acc[mf][nf][1]);
            *reinterpret_cast<float2*>(&C[(size_t)(row + 8) * ldc + col]) =
                make_float2(acc[mf][nf][2], acc[mf][nf][3]);
        }
    }
}

__global__ void __launch_bounds__(256, 2)
mma_nt(const float* __restrict__ A, const float* __restrict__ B, float* __restrict__ C,
       int K, int lda, int ldb, int ldc) {
    __shared__ MSmem s;
    mma_core(A, B, C, K, lda, ldb, ldc, blockIdx.x * MBM, blockIdx.y * MBN, s);
}

__global__ void __launch_bounds__(256, 2)
mma_scores(const float* __restrict__ q, const float* __restrict__ k, float* __restrict__ sc) {
    if (blockIdx.y > blockIdx.x) return;
    int z = blockIdx.z;
    int b = z >> 3, h = z & 7;
    const float* A = q + (size_t)z * T_ * HD_;
    const float* B = k + (size_t)(b * NKV_ + (h >> 2)) * T_ * HD_;
    float* C = sc + (size_t)z * T_ * T_;
    __shared__ MSmem s;
    mma_core(A, B, C, HD_, HD_, HD_, T_, blockIdx.x * MBM, blockIdx.y * MBN, s);
}

__global__ void __launch_bounds__(256, 2)
mma_attnv(const float* __restrict__ p, const float* __restrict__ vT, float* __restrict__ o) {
    int z = blockIdx.z;
    int b = z >> 3, h = z & 7;
    const float* A = p + (size_t)z * T_ * T_;
    const float* B = vT + (size_t)(b * NKV_ + (h >> 2)) * HD_ * T_;
    float* C = o + (size_t)b * T_ * H_ + (size_t)h * HD_;
    int bm = blockIdx.x * MBM;
    __shared__ MSmem s;
    mma_core(A, B, C, bm + MBM, T_, T_, H_, bm, blockIdx.y * MBN, s);
}

// laurel1: C[2048,64] = A[2048,2048] @ B[64,2048]^T, split-K x4
__global__ void __launch_bounds__(256)
laurel1_kernel(const float* __restrict__ A, const float* __restrict__ B, float* __restrict__ P) {
    __shared__ float Bs[64][65];
    __shared__ float As[32][65];
    int tid = threadIdx.x;
    int bm = blockIdx.x * 32;
    int ks = blockIdx.y;
    int kbeg = ks * (H_ / 4), kend = kbeg + H_ / 4;
    float acc0[4] = {0.f, 0.f, 0.f, 0.f};
    float acc1[4] = {0.f, 0.f, 0.f, 0.f};
    int tn = tid & 15;
    int tr = tid >> 4;
    for (int k0 = kbeg; k0 < kend; k0 += 64) {
        for (int i = tid; i < 64 * 64; i += 256) {
            int n = i >> 6, kk = i & 63;
            Bs[n][kk] = B[(size_t)n * H_ + k0 + kk];
        }
        for (int i = tid; i < 32 * 64; i += 256) {
            int r = i >> 6, kk = i & 63;
            As[r][kk] = A[(size_t)(bm + r) * H_ + k0 + kk];
        }
        __syncthreads();
#pragma unroll 8
        for (int kk = 0; kk < 64; kk++) {
            float a0 = As[tr][kk], a1 = As[tr + 16][kk];
#pragma unroll
            for (int j = 0; j < 4; j++) {
                float bv = Bs[tn * 4 + j][kk];
                acc0[j] = fmaf(a0, bv, acc0[j]);
                acc1[j] = fmaf(a1, bv, acc1[j]);
            }
        }
        __syncthreads();
    }
#pragma unroll
    for (int j = 0; j < 4; j++) {
        P[((size_t)ks * BT_ + bm + tr) * LR_ + tn * 4 + j] = acc0[j];
        P[((size_t)ks * BT_ + bm + tr + 16) * LR_ + tn * 4 + j] = acc1[j];
    }
}

__global__ void laurel1_reduce(const float* __restrict__ P, float* __restrict__ out) {
    int i = blockIdx.x * blockDim.x + threadIdx.x;
    if (i >= BT_ * LR_) return;
    out[i] = P[i] + P[BT_ * LR_ + i] + P[2 * BT_ * LR_ + i] + P[3 * BT_ * LR_ + i];
}

extern "C" void kernel_launch(void* const* d_in, const int* in_sizes, int n_in,
                              void* d_out, int out_size) {
    const float* hs    = (const float*)d_in[0];
    const float* cosb  = (const float*)d_in[1];
    const float* sinb  = (const float*)d_in[2];
    const float* wq    = (const float*)d_in[3];
    const float* wk    = (const float*)d_in[4];
    const float* wv    = (const float*)d_in[5];
    const float* wo    = (const float*)d_in[6];
    const float* qnw   = (const float*)d_in[7];
    const float* knw   = (const float*)d_in[8];
    const float* in_ln = (const float*)d_in[9];
    const float* pa_ln = (const float*)d_in[10];
    const float* pf_ln = (const float*)d_in[11];
    const float* pw_ln = (const float*)d_in[12];
    const float* gatew = (const float*)d_in[13];
    const float* upw   = (const float*)d_in[14];
    const float* downw = (const float*)d_in[15];
    const float* llw   = (const float*)d_in[16];
    const float* lrw   = (const float*)d_in[17];
    const float* lnw   = (const float*)d_in[18];
    const float* rnw   = (const float*)d_in[19];
    const float* rw    = (const float*)d_in[20];
    const float* pcw   = (const float*)d_in[21];
    const float* ccw   = (const float*)d_in[22];
    const float* cscal = (const float*)d_in[23];
    float* out = (float*)d_out;

    Scratch* S = 0;
    cudaGetSymbolAddress((void**)&S, g_scratch);

    router_kernel<<<BT_, 256>>>(hs, rnw, rw, S->m);
    predict_kernel<<<BT_, 256>>>(hs, S->m, pcw, S->pred);
    ln_kernel<<<BT_, 256>>>(S->pred, in_ln, (const float*)0, (const float*)0, 1.f, S->xnorm);

    laurel1_kernel<<<dim3(BT_ / 32, 4), 256>>>(S->xnorm, llw, S->lrpart);
    laurel1_reduce<<<(BT_ * LR_ + 255) / 256, 256>>>(S->lrpart, S->lrbuf);
    mma_nt<<<dim3(16, 16), 256>>>(S->lrbuf, lrw, S->laurel, LR_, LR_, LR_, H_);
    ln_kernel<<<BT_, 256>>>(S->laurel, lnw, S->xnorm, (const float*)0, 1.f, S->laurel);

    mma_nt<<<dim3(16, 16), 256>>>(S->xnorm, wq, S->qraw, H_, H_, H_, NH_ * HD_);
    mma_nt<<<dim3(16, 4), 256>>>(S->xnorm, wk, S->kraw, H_, H_, H_, NKV_ * HD_);
    mma_nt<<<dim3(16, 4), 256>>>(S->xnorm, wv, S->vraw, H_, H_, H_, NKV_ * HD_);
    qkvpost_kernel<<<BT_ * NH_, 256>>>(S->qraw, qnw, cosb, sinb, S->q, NH_, 1, 0);
    qkvpost_kernel<<<BT_ * NKV_, 256>>>(S->kraw, knw, cosb, sinb, S->k, NKV_, 1, 0);
    qkvpost_kernel<<<BT_ * NKV_, 256>>>(S->vraw, (const float*)0, cosb, sinb, S->vT, NKV_, 0, 1);

    mma_scores<<<dim3(8, 8, B_ * NH_), 256>>>(S->q, S->k, S->scores);
    softmax_kernel<<<B_ * NH_ * T_, 256>>>(S->scores);
    mma_attnv<<<dim3(8, 2, B_ * NH_), 256>>>(S->scores, S->vT, S->attnout);
    mma_nt<<<dim3(16, 16), 256>>>(S->attnout, wo, S->attnproj,
                                  NH_ * HD_, NH_ * HD_, NH_ * HD_, H_);

    ln_kernel<<<BT_, 256>>>(S->attnproj, pa_ln, S->pred, S->laurel,
                            0.7071067811865476f, S->attnlaurel);
    ln_kernel<<<BT_, 256>>>(S->attnlaurel, pf_ln, (const float*)0, (const float*)0, 1.f, S->hn);

    mma_nt<<<dim3(16, 64), 256>>>(S->hn, gatew, S->gate, H_, H_, H_, FF_);
    mma_nt<<<dim3(16, 64), 256>>>(S->hn, upw, S->up, H_, H_, H_, FF_);

    int n4 = (int)(((size_t)BT_ * FF_) / 4);
    gelumul_kernel<<<(n4 + 255) / 256, 256>>>(S->gate, S->up, n4);

    mma_nt<<<dim3(16, 16), 256>>>(S->gate, downw, S->ffw, FF_, FF_, FF_, H_);
    ln_kernel<<<BT_, 256>>>(S->ffw, pw_ln, S->attnlaurel, (const float*)0, 1.f, S->act);

    router_kernel<<<BT_, 256>>>(S->act, rnw, rw, S->mc);
    correct_kernel<<<BT_, 256>>>(S->act, S->pred, S->mc, ccw, cscal, out);

    (void)in_sizes; (void)n_in; (void)out_size;
}